// round 15
// baseline (speedup 1.0000x reference)
#include <cuda_runtime.h>
#include <math.h>

#define BB 8
#define NN 256
#define DD 128
#define ROWS (BB*NN)          // 2048
#define EROWS (BB*NN*NN)      // 524288
#define BN_EPS 1e-5f
#define RPW 8                 // e-rows per warp in copy kernel
#define TI  4                 // i-rows per tail block
#define NB_TAIL (ROWS/TI)     // 512 tail blocks
#define NB_COPY  8192
#define NB_HW    512          // copy blocks 1..512 compute HW (4 rows each)

// __device__ globals (zero at load; stats/barrier re-zeroed by copy block 0
// every launch, stream-ordered before the tail -> graph-replay safe)
__device__ float  g_w[EROWS];
__device__ float4 g_hp[BB*(NN/4)*DD];  // packed HW: [b][j4][t] = HW[b,4j4..+3,t]
__device__ float  g_sum[DD];
__device__ float  g_sumsq[DD];
__device__ int    g_bar;

// ---------------------------------------------------------------------------
// Kernel 1: norm + copy of e (6.4 TB/s hot path; regs ~40, 6 blocks/SM).
// Block 0: zero stats/barrier.
// Blocks 1..512: HW = h @ W^T, 4 rows each (tiny per-block work, no long
// poles; amortized over ~9 waves of the copy stream).
//   HW[j][k] = sum_d h[j][d] * W[k][d]
// ---------------------------------------------------------------------------
__global__ void __launch_bounds__(256) k_norm_copy(
    const float4* __restrict__ e,
    float4* __restrict__ out_e,
    const float* __restrict__ Wm,
    const float* __restrict__ h)
{
    if (blockIdx.x == 0) {
        if (threadIdx.x < DD) {
            g_sum[threadIdx.x]   = 0.0f;
            g_sumsq[threadIdx.x] = 0.0f;
            if (threadIdx.x == 0) g_bar = 0;
        }
    } else if (blockIdx.x <= NB_HW) {
        int m  = blockIdx.x - 1;            // 0..511
        int b  = m >> 6;                    // batch (64 blocks per batch)
        int jb = (m & 63) * 4;              // first of 4 rows
        int k  = threadIdx.x & 127;         // output feature
        int rg = threadIdx.x >> 7;          // half: 2 rows each
        int j0 = jb + rg * 2;

        const float4* hb4 = (const float4*)(h + (size_t)b * NN * DD);
        const float4* Wm4 = (const float4*)Wm;

        float a0 = 0.0f, a1 = 0.0f;
        #pragma unroll 8
        for (int d4 = 0; d4 < DD/4; d4++) {
            float4 wv = Wm4[k * (DD/4) + d4];          // L1/L2-hot
            float4 x0 = hb4[(j0 + 0) * (DD/4) + d4];
            float4 x1 = hb4[(j0 + 1) * (DD/4) + d4];
            a0 = fmaf(x0.x, wv.x, a0); a0 = fmaf(x0.y, wv.y, a0);
            a0 = fmaf(x0.z, wv.z, a0); a0 = fmaf(x0.w, wv.w, a0);
            a1 = fmaf(x1.x, wv.x, a1); a1 = fmaf(x1.y, wv.y, a1);
            a1 = fmaf(x1.z, wv.z, a1); a1 = fmaf(x1.w, wv.w, a1);
        }
        // packed layout: g_hp[b][j>>2][k] component (j&3);  jb is 4-aligned
        float* hp = (float*)(g_hp + (size_t)b * (NN/4) * DD);
        int base4 = (jb >> 2) * DD;
        hp[(base4 + k) * 4 + (j0 & 3)]       = a0;
        hp[(base4 + k) * 4 + ((j0 + 1) & 3)] = a1;
    }

    size_t gw   = (size_t)((blockIdx.x * blockDim.x + threadIdx.x) >> 5);
    int    lane = threadIdx.x & 31;
    size_t r0i  = gw * RPW;
    size_t base = r0i * 32 + lane;

    float4 v[RPW];
    #pragma unroll
    for (int k = 0; k < RPW; k++)
        v[k] = __ldcs(e + base + (size_t)k * 32);
    #pragma unroll
    for (int k = 0; k < RPW; k++)
        __stcs(out_e + base + (size_t)k * 32, v[k]);

    float s[RPW];
    #pragma unroll
    for (int k = 0; k < RPW; k++)
        s[k] = v[k].x*v[k].x + v[k].y*v[k].y + v[k].z*v[k].z + v[k].w*v[k].w;
    #pragma unroll
    for (int o = 16; o > 0; o >>= 1) {
        #pragma unroll
        for (int k = 0; k < RPW; k++)
            s[k] += __shfl_xor_sync(0xffffffffu, s[k], o);
    }
    if (lane == 0) {
        #pragma unroll
        for (int k = 0; k < RPW; k++)
            g_w[r0i + k] = sqrtf(s[k]);
    }
}

// ---------------------------------------------------------------------------
// Kernel 2: tail (linear folded into HW; measured 16.9us). 512 blocks x 256.
//   A: softmax (warps 0-3, float4 loads)
//   B: agg over packed HW — half owns 32 j4's for ALL 4 rows, MLP=8
//   C: y = relu(HW[i] + agg + bias); BN stats -> grid barrier -> BN apply
// ---------------------------------------------------------------------------
__global__ void __launch_bounds__(256, 4) k_tail(
    const float* __restrict__ h,
    const float* __restrict__ bias,
    const float* __restrict__ gamma,
    const float* __restrict__ beta,
    float* __restrict__ out_h)
{
    int bi0 = blockIdx.x * TI;
    int b   = bi0 >> 8;
    int i0  = bi0 & 255;
    int tid = threadIdx.x;
    int t    = tid & 127;
    int half = tid >> 7;
    int warp = tid >> 5, lane = tid & 31;

    __shared__ float sw[TI][NN];          // softmax probs (4 KB)
    __shared__ float spart[2][TI][DD];    // agg partials  (4 KB)
    __shared__ float pp[DD], pps[DD];     // BN partials   (1 KB)

    // --- A: softmax, warps 0-3 own one row each; float4 loads ---
    if (warp < TI) {
        const float4* wrow4 = (const float4*)(g_w + (size_t)(bi0 + warp) * NN);
        float4 a = wrow4[lane * 2];
        float4 c = wrow4[lane * 2 + 1];
        float m = fmaxf(fmaxf(fmaxf(a.x, a.y), fmaxf(a.z, a.w)),
                        fmaxf(fmaxf(c.x, c.y), fmaxf(c.z, c.w)));
        #pragma unroll
        for (int o = 16; o > 0; o >>= 1)
            m = fmaxf(m, __shfl_xor_sync(0xffffffffu, m, o));
        a.x = __expf(a.x - m); a.y = __expf(a.y - m);
        a.z = __expf(a.z - m); a.w = __expf(a.w - m);
        c.x = __expf(c.x - m); c.y = __expf(c.y - m);
        c.z = __expf(c.z - m); c.w = __expf(c.w - m);
        float sum = a.x + a.y + a.z + a.w + c.x + c.y + c.z + c.w;
        #pragma unroll
        for (int o = 16; o > 0; o >>= 1)
            sum += __shfl_xor_sync(0xffffffffu, sum, o);
        float inv = 1.0f / sum;
        a.x *= inv; a.y *= inv; a.z *= inv; a.w *= inv;
        c.x *= inv; c.y *= inv; c.z *= inv; c.w *= inv;
        float4* swr4 = (float4*)&sw[warp][0];
        swr4[lane * 2]     = a;
        swr4[lane * 2 + 1] = c;
    }
    __syncthreads();

    // --- B: agg over packed HW. half owns j4 in [32h, 32h+32); MLP=8 ---
    {
        const float4* hp = g_hp + (size_t)b * (NN/4) * DD;
        float acc[TI] = {0.f, 0.f, 0.f, 0.f};
        int j4b = half * 32;
        #pragma unroll
        for (int cch = 0; cch < 4; cch++) {
            float4 hv[8];
            #pragma unroll
            for (int k = 0; k < 8; k++)
                hv[k] = hp[(j4b + cch*8 + k) * DD + t];
            #pragma unroll
            for (int k = 0; k < 8; k++) {
                int j4 = j4b + cch*8 + k;
                #pragma unroll
                for (int r = 0; r < TI; r++) {
                    float4 p = *(const float4*)&sw[r][j4 * 4];  // broadcast
                    acc[r] = fmaf(p.x, hv[k].x, acc[r]);
                    acc[r] = fmaf(p.y, hv[k].y, acc[r]);
                    acc[r] = fmaf(p.z, hv[k].z, acc[r]);
                    acc[r] = fmaf(p.w, hv[k].w, acc[r]);
                }
            }
        }
        #pragma unroll
        for (int r = 0; r < TI; r++)
            spart[half][r][t] = acc[r];
    }
    __syncthreads();

    // --- C: y = relu(HW[i] + agg + bias); half owns rows {2h, 2h+1} ---
    const float* hb  = h + (size_t)b * NN * DD;
    const float* hpf = (const float*)(g_hp + (size_t)b * (NN/4) * DD);
    float y[2], hres[2];
    float bt = bias[t];
    float ls = 0.0f, lss = 0.0f;
    #pragma unroll
    for (int rr = 0; rr < 2; rr++) {
        int r   = half * 2 + rr;
        int row = i0 + r;
        hres[rr] = hb[row * DD + t];
        float hwown = hpf[(((row >> 2) * DD) + t) * 4 + (row & 3)];
        y[rr] = fmaxf(bt + hwown + spart[0][r][t] + spart[1][r][t], 0.0f);
        ls  += y[rr];
        lss  = fmaf(y[rr], y[rr], lss);
    }
    if (half == 1) { pp[t] = ls; pps[t] = lss; }
    __syncthreads();
    if (half == 0) {
        atomicAdd(&g_sum[t],   ls  + pp[t]);
        atomicAdd(&g_sumsq[t], lss + pps[t]);
    }

    // --- grid barrier (512 blocks co-resident by launch_bounds(256,4)) ---
    __syncthreads();
    if (tid == 0) {
        __threadfence();
        atomicAdd(&g_bar, 1);
        while (atomicAdd(&g_bar, 0) < NB_TAIL) __nanosleep(64);
    }
    __syncthreads();
    __threadfence();

    // --- BN apply + residual straight from registers ---
    float s  = __ldcg(&g_sum[t]);
    float ss = __ldcg(&g_sumsq[t]);
    float mean = s * (1.0f / ROWS);
    float var  = ss * (1.0f / ROWS) - mean * mean;
    float g  = gamma[t] * rsqrtf(var + BN_EPS);
    float b2 = beta[t] - mean * g;
    #pragma unroll
    for (int rr = 0; rr < 2; rr++) {
        int r = half * 2 + rr;
        out_h[(bi0 + r) * DD + t] = fmaf(y[rr], g, b2) + hres[rr];
    }
}

// ---------------------------------------------------------------------------
extern "C" void kernel_launch(void* const* d_in, const int* in_sizes, int n_in,
                              void* d_out, int out_size) {
    const float* h     = (const float*)d_in[0];   // (8,256,128)
    const float* e     = (const float*)d_in[1];   // (8,256,256,128)
    const float* Wm    = (const float*)d_in[2];   // (128,128)
    const float* bias  = (const float*)d_in[3];   // (128)
    const float* gamma = (const float*)d_in[4];   // (128)
    const float* beta  = (const float*)d_in[5];   // (128)

    float* out_h = (float*)d_out;                 // (8,256,128) first
    float* out_e = out_h + (size_t)ROWS * DD;     // then (8,256,256,128)

    k_norm_copy<<<NB_COPY, 256>>>((const float4*)e, (float4*)out_e, Wm, h);
    k_tail<<<NB_TAIL, 256>>>(h, bias, gamma, beta, out_h);
}

// round 16
// speedup vs baseline: 1.0873x; 1.0873x over previous
#include <cuda_runtime.h>
#include <math.h>

#define BB 8
#define NN 256
#define DD 128
#define ROWS (BB*NN)          // 2048
#define EROWS (BB*NN*NN)      // 524288
#define BN_EPS 1e-5f
#define RPW 8                 // e-rows per warp in copy kernel
#define TI  4                 // i-rows per tail block
#define NB_TAIL (ROWS/TI)     // 512 tail blocks
#define NB_COPY  8192

typedef unsigned long long u64;

// packed f32x2 FMA (sm_100+; PTX-only — halves FMA issue count)
__device__ __forceinline__ u64 fma2(u64 a, u64 b, u64 c) {
    u64 d;
    asm("fma.rn.f32x2 %0, %1, %2, %3;" : "=l"(d) : "l"(a), "l"(b), "l"(c));
    return d;
}
__device__ __forceinline__ float f2sum(u64 a) {
    float2 f = *reinterpret_cast<float2*>(&a);
    return f.x + f.y;
}

// __device__ globals (zero at load; stats/barrier re-zeroed by copy block 0
// every launch, stream-ordered before the tail -> graph-replay safe)
__device__ float  g_w[EROWS];
__device__ float4 g_Wtp[(DD/4)*DD];    // packed W: [d4][t] = W[t][4d4..+3]
__device__ float4 g_hp[BB*(NN/4)*DD];  // packed h: [b][j4][t] = h[b][4j4..+3][t]
__device__ float  g_sum[DD];
__device__ float  g_sumsq[DD];
__device__ int    g_bar;

// ---------------------------------------------------------------------------
// Kernel 1: EXACT R13 copy kernel (75.8us / 80% of spec, 40 regs, 6 blk/SM).
// Block 0: zero stats/barrier + pack W.  Blocks 1..8: pack h per batch.
// ---------------------------------------------------------------------------
__global__ void __launch_bounds__(256) k_norm_copy(
    const float4* __restrict__ e,
    float4* __restrict__ out_e,
    const float* __restrict__ Wm,
    const float* __restrict__ h)
{
    if (blockIdx.x == 0) {
        if (threadIdx.x < DD) {
            g_sum[threadIdx.x]   = 0.0f;
            g_sumsq[threadIdx.x] = 0.0f;
            if (threadIdx.x == 0) g_bar = 0;
        }
        for (int i = threadIdx.x; i < DD * (DD/4); i += 256) {
            int t  = i / (DD/4);
            int d4 = i % (DD/4);
            g_Wtp[d4 * DD + t] = ((const float4*)Wm)[t * (DD/4) + d4];
        }
    } else if (blockIdx.x <= BB) {
        int b = blockIdx.x - 1;
        const float4* hb4 = (const float4*)(h + (size_t)b * NN * DD);
        float4* out = g_hp + (size_t)b * (NN/4) * DD;
        for (int tile = threadIdx.x; tile < (NN/4)*(DD/4); tile += 256) {
            int j4 = tile >> 5;
            int t4 = tile & 31;
            float4 r0 = hb4[(j4*4 + 0) * (DD/4) + t4];
            float4 r1 = hb4[(j4*4 + 1) * (DD/4) + t4];
            float4 r2 = hb4[(j4*4 + 2) * (DD/4) + t4];
            float4 r3 = hb4[(j4*4 + 3) * (DD/4) + t4];
            out[j4 * DD + t4*4 + 0] = make_float4(r0.x, r1.x, r2.x, r3.x);
            out[j4 * DD + t4*4 + 1] = make_float4(r0.y, r1.y, r2.y, r3.y);
            out[j4 * DD + t4*4 + 2] = make_float4(r0.z, r1.z, r2.z, r3.z);
            out[j4 * DD + t4*4 + 3] = make_float4(r0.w, r1.w, r2.w, r3.w);
        }
    }
    size_t gw   = (size_t)((blockIdx.x * blockDim.x + threadIdx.x) >> 5);
    int    lane = threadIdx.x & 31;
    size_t r0i  = gw * RPW;
    size_t base = r0i * 32 + lane;

    float4 v[RPW];
    #pragma unroll
    for (int k = 0; k < RPW; k++)
        v[k] = __ldcs(e + base + (size_t)k * 32);
    #pragma unroll
    for (int k = 0; k < RPW; k++)
        __stcs(out_e + base + (size_t)k * 32, v[k]);

    float s[RPW];
    #pragma unroll
    for (int k = 0; k < RPW; k++)
        s[k] = v[k].x*v[k].x + v[k].y*v[k].y + v[k].z*v[k].z + v[k].w*v[k].w;
    #pragma unroll
    for (int o = 16; o > 0; o >>= 1) {
        #pragma unroll
        for (int k = 0; k < RPW; k++)
            s[k] += __shfl_xor_sync(0xffffffffu, s[k], o);
    }
    if (lane == 0) {
        #pragma unroll
        for (int k = 0; k < RPW; k++)
            g_w[r0i + k] = sqrtf(s[k]);
    }
}

// ---------------------------------------------------------------------------
// Kernel 2: tail = R13 structure with f32x2 split accumulators.
// 512 blocks x 256 threads, launch_bounds(256,4) (barrier-safe co-residency).
//   A: softmax (warps 0-3, float4 loads)
//   B: agg — half owns 32 j4's for all 4 rows; LDS.128 as ulonglong2 gives
//      (even,odd) j-pairs; 2 FMA2 per (j4,r) instead of 4 FMA.
//   C: sx build
//   D: linear — same trick over d-pairs via g_Wtp: 2 FMA2 per (d4,r).
//   E: relu, BN stats -> grid barrier -> BN apply from registers.
// ---------------------------------------------------------------------------
__global__ void __launch_bounds__(256, 4) k_tail(
    const float* __restrict__ h,
    const float* __restrict__ bias,
    const float* __restrict__ gamma,
    const float* __restrict__ beta,
    float* __restrict__ out_h)
{
    int bi0 = blockIdx.x * TI;
    int b   = bi0 >> 8;
    int i0  = bi0 & 255;
    int tid = threadIdx.x;
    int t    = tid & 127;
    int half = tid >> 7;
    int warp = tid >> 5, lane = tid & 31;

    __shared__ float sw[TI][NN];          // softmax probs   (4 KB, 16B-aligned rows)
    __shared__ float spart[2][TI][DD];    // agg partials    (4 KB)
    __shared__ float sx[TI][DD];          // pre-linear acts (2 KB, 16B-aligned rows)
    __shared__ float splin[2][TI][DD];    // linear partials (4 KB)
    __shared__ float pp[DD], pps[DD];     // BN partials     (1 KB)

    // --- A: softmax, warps 0-3 own one row each; float4 loads ---
    if (warp < TI) {
        const float4* wrow4 = (const float4*)(g_w + (size_t)(bi0 + warp) * NN);
        float4 a = wrow4[lane * 2];
        float4 c = wrow4[lane * 2 + 1];
        float m = fmaxf(fmaxf(fmaxf(a.x, a.y), fmaxf(a.z, a.w)),
                        fmaxf(fmaxf(c.x, c.y), fmaxf(c.z, c.w)));
        #pragma unroll
        for (int o = 16; o > 0; o >>= 1)
            m = fmaxf(m, __shfl_xor_sync(0xffffffffu, m, o));
        a.x = __expf(a.x - m); a.y = __expf(a.y - m);
        a.z = __expf(a.z - m); a.w = __expf(a.w - m);
        c.x = __expf(c.x - m); c.y = __expf(c.y - m);
        c.z = __expf(c.z - m); c.w = __expf(c.w - m);
        float sum = a.x + a.y + a.z + a.w + c.x + c.y + c.z + c.w;
        #pragma unroll
        for (int o = 16; o > 0; o >>= 1)
            sum += __shfl_xor_sync(0xffffffffu, sum, o);
        float inv = 1.0f / sum;
        a.x *= inv; a.y *= inv; a.z *= inv; a.w *= inv;
        c.x *= inv; c.y *= inv; c.z *= inv; c.w *= inv;
        float4* swr4 = (float4*)&sw[warp][0];
        swr4[lane * 2]     = a;
        swr4[lane * 2 + 1] = c;
    }
    __syncthreads();

    // --- B: agg with f32x2 split accumulators (even/odd j in the 2 lanes) ---
    {
        const ulonglong2* hp =
            (const ulonglong2*)(g_hp + (size_t)b * (NN/4) * DD);
        u64 acc2[TI] = {0ull, 0ull, 0ull, 0ull};
        int j4b = half * 32;
        #pragma unroll
        for (int cch = 0; cch < 4; cch++) {
            ulonglong2 hv[8];
            #pragma unroll
            for (int k = 0; k < 8; k++)
                hv[k] = hp[(j4b + cch*8 + k) * DD + t];
            #pragma unroll
            for (int k = 0; k < 8; k++) {
                int j4 = j4b + cch*8 + k;
                #pragma unroll
                for (int r = 0; r < TI; r++) {
                    ulonglong2 p = *(const ulonglong2*)&sw[r][j4 * 4];
                    acc2[r] = fma2(p.x, hv[k].x, acc2[r]);
                    acc2[r] = fma2(p.y, hv[k].y, acc2[r]);
                }
            }
        }
        #pragma unroll
        for (int r = 0; r < TI; r++)
            spart[half][r][t] = f2sum(acc2[r]);
    }
    __syncthreads();

    // --- C: build sx; half owns rows {2h, 2h+1} residuals ---
    const float* hb = h + (size_t)b * NN * DD;
    float hres[2];
    #pragma unroll
    for (int rr = 0; rr < 2; rr++) {
        int r = half * 2 + rr;
        hres[rr] = hb[(i0 + r) * DD + t];
        sx[r][t] = hres[rr] + spart[0][r][t] + spart[1][r][t];
    }
    __syncthreads();

    // --- D: linear partials with f32x2 (even/odd d in the 2 lanes) ---
    {
        u64 lp2[TI] = {0ull, 0ull, 0ull, 0ull};
        const ulonglong2* Wu = (const ulonglong2*)g_Wtp;
        int d4b = half * 16;
        #pragma unroll
        for (int cch = 0; cch < 4; cch++) {
            ulonglong2 wt[4];
            #pragma unroll
            for (int k = 0; k < 4; k++)
                wt[k] = Wu[(d4b + cch*4 + k) * DD + t];
            #pragma unroll
            for (int k = 0; k < 4; k++) {
                int d4 = d4b + cch*4 + k;
                #pragma unroll
                for (int r = 0; r < TI; r++) {
                    ulonglong2 xv = *(const ulonglong2*)&sx[r][d4 * 4];
                    lp2[r] = fma2(xv.x, wt[k].x, lp2[r]);
                    lp2[r] = fma2(xv.y, wt[k].y, lp2[r]);
                }
            }
        }
        #pragma unroll
        for (int r = 0; r < TI; r++)
            splin[half][r][t] = f2sum(lp2[r]);
    }
    __syncthreads();

    // --- E: combine, relu, BN stats; half owns rows {2h, 2h+1} ---
    float y[2];
    float bt = bias[t];
    float ls = 0.0f, lss = 0.0f;
    #pragma unroll
    for (int rr = 0; rr < 2; rr++) {
        int r = half * 2 + rr;
        y[rr] = fmaxf(bt + splin[0][r][t] + splin[1][r][t], 0.0f);
        ls  += y[rr];
        lss  = fmaf(y[rr], y[rr], lss);
    }
    if (half == 1) { pp[t] = ls; pps[t] = lss; }
    __syncthreads();
    if (half == 0) {
        atomicAdd(&g_sum[t],   ls  + pp[t]);
        atomicAdd(&g_sumsq[t], lss + pps[t]);
    }

    // --- grid barrier (512 blocks co-resident by launch_bounds(256,4)) ---
    __syncthreads();
    if (tid == 0) {
        __threadfence();
        atomicAdd(&g_bar, 1);
        while (atomicAdd(&g_bar, 0) < NB_TAIL) __nanosleep(64);
    }
    __syncthreads();
    __threadfence();

    // --- BN apply + residual straight from registers ---
    float s  = __ldcg(&g_sum[t]);
    float ss = __ldcg(&g_sumsq[t]);
    float mean = s * (1.0f / ROWS);
    float var  = ss * (1.0f / ROWS) - mean * mean;
    float g  = gamma[t] * rsqrtf(var + BN_EPS);
    float b2 = beta[t] - mean * g;
    #pragma unroll
    for (int rr = 0; rr < 2; rr++) {
        int r = half * 2 + rr;
        out_h[(bi0 + r) * DD + t] = fmaf(y[rr], g, b2) + hres[rr];
    }
}

// ---------------------------------------------------------------------------
extern "C" void kernel_launch(void* const* d_in, const int* in_sizes, int n_in,
                              void* d_out, int out_size) {
    const float* h     = (const float*)d_in[0];   // (8,256,128)
    const float* e     = (const float*)d_in[1];   // (8,256,256,128)
    const float* Wm    = (const float*)d_in[2];   // (128,128)
    const float* bias  = (const float*)d_in[3];   // (128)
    const float* gamma = (const float*)d_in[4];   // (128)
    const float* beta  = (const float*)d_in[5];   // (128)

    float* out_h = (float*)d_out;                 // (8,256,128) first
    float* out_e = out_h + (size_t)ROWS * DD;     // then (8,256,256,128)

    k_norm_copy<<<NB_COPY, 256>>>((const float4*)e, (float4*)out_e, Wm, h);
    k_tail<<<NB_TAIL, 256>>>(h, bias, gamma, beta, out_h);
}